// round 8
// baseline (speedup 1.0000x reference)
#include <cuda_runtime.h>
#include <math.h>

#define Bsz 16
#define Tn 16
#define FDIM 64
#define ODIM 8
#define NQ 10
#define NA 4
#define NROTS 80
#define QROTS 40
#define NS 1024
#define NANC 16
#define STATE_PER_B (NS*NANC)
#define TOTAL_AMPS (Bsz*STATE_PER_B)

typedef unsigned long long u64;

__device__ float4 g_state4[TOTAL_AMPS/2];
#define G_STATE  ((float2*)g_state4)
#define G_STATEU ((u64*)g_state4)
__device__ float2 g_csn[Bsz*Tn*NROTS];
__device__ float2 g_qff[QROTS];
__device__ float2 g_M[3][256];
__device__ float2 g_v0[16];

// ------------------------------------------------------- packed f32x2 ops ---
__device__ __forceinline__ u64 pk2(float x, float y) {
    u64 r; asm("mov.b64 %0, {%1, %2};" : "=l"(r) : "f"(x), "f"(y)); return r;
}
__device__ __forceinline__ float2 upk(u64 a) {
    float2 f; asm("mov.b64 {%0, %1}, %2;" : "=f"(f.x), "=f"(f.y) : "l"(a)); return f;
}
__device__ __forceinline__ u64 mul2(u64 a, u64 b) {
    u64 d; asm("mul.rn.f32x2 %0, %1, %2;" : "=l"(d) : "l"(a), "l"(b)); return d;
}
__device__ __forceinline__ u64 fma2(u64 a, u64 b, u64 c) {
    u64 d; asm("fma.rn.f32x2 %0, %1, %2, %3;" : "=l"(d) : "l"(a), "l"(b), "l"(c)); return d;
}
__device__ __forceinline__ u64 swap2(u64 a) {
    float2 f = upk(a); return pk2(f.y, f.x);
}

// -------------------------------------------------- pre (angles + setup) ----
__global__ void __launch_bounds__(256) k_pre(const float* __restrict__ x,
                                             const float* __restrict__ Wfp,
                                             const float* __restrict__ bfp,
                                             const float* __restrict__ prep_p,
                                             const float* __restrict__ sig_ang,
                                             const float* __restrict__ qff_p)
{
    int tid = threadIdx.x;
    if (blockIdx.x < 256) {
        int bt = blockIdx.x;
        int b = bt >> 4, t = bt & 15;
        __shared__ float h[64];
        if (tid < 64) {
            int f = tid;
            int k = f >> 1;
            float div = expf((float)(2*k) * (-logf(10000.0f) / 64.0f));
            float arg = (float)t * div;
            float pe = (f & 1) ? cosf(arg) : sinf(arg);
            h[f] = x[(b*64 + f)*16 + t] + pe;
        }
        __syncthreads();
        if (tid < NROTS) {
            float acc = bfp[tid];
            const float* w = Wfp + tid*64;
            #pragma unroll
            for (int f = 0; f < 64; ++f) acc += h[f]*w[f];
            float sg = 1.0f / (1.0f + expf(-acc));
            float sn, cs;
            sincosf(3.14159265358979323846f * sg, &sn, &cs);
            g_csn[bt*NROTS + tid] = make_float2(cs, sn);
        }
        return;
    }
    __shared__ float2 sU[16][16];
    int t = tid;
    if (t < 16) {
        float2 v[16];
        #pragma unroll
        for (int i = 0; i < 16; ++i) v[i] = make_float2(0.f, 0.f);
        v[t] = make_float2(1.f, 0.f);
        for (int ly = 0; ly < 4; ++ly) {
            for (int qi = 0; qi < 4; ++qi) {
                int p = 3 - qi;
                float thy = prep_p[(ly*4 + qi)*2 + 0];
                float thz = prep_p[(ly*4 + qi)*2 + 1];
                float c, s;
                sincosf(0.5f*thy, &s, &c);
                for (int m = 0; m < 8; ++m) {
                    int i0 = ((m >> p) << (p+1)) | (m & ((1 << p) - 1));
                    int i1 = i0 | (1 << p);
                    float2 a0 = v[i0], a1 = v[i1];
                    v[i0] = make_float2(c*a0.x - s*a1.x, c*a0.y - s*a1.y);
                    v[i1] = make_float2(s*a0.x + c*a1.x, s*a0.y + c*a1.y);
                }
                float cz, sz;
                sincosf(0.5f*thz, &sz, &cz);
                for (int i = 0; i < 16; ++i) {
                    float im = ((i >> p) & 1) ? sz : -sz;
                    float2 a = v[i];
                    v[i] = make_float2(cz*a.x - im*a.y, cz*a.y + im*a.x);
                }
            }
            for (int i = 0; i < 3; ++i) {
                int pc = 3 - i, pt = 2 - i;
                for (int idx = 0; idx < 16; ++idx) {
                    if (((idx >> pc) & 1) == 1 && ((idx >> pt) & 1) == 0) {
                        int j = idx | (1 << pt);
                        float2 tmp = v[idx]; v[idx] = v[j]; v[j] = tmp;
                    }
                }
            }
        }
        #pragma unroll
        for (int r = 0; r < 16; ++r) sU[r][t] = v[r];
    }
    __syncthreads();
    if (t < 16) {
        float c0, s0;
        sincosf(sig_ang[0], &s0, &c0);
        float2 u = sU[t][0];
        g_v0[t] = make_float2(c0*u.x - s0*u.y, c0*u.y + s0*u.x);
    }
    if (t >= 192 && t < 192 + QROTS) {
        float c, s;
        sincosf(0.5f * qff_p[t - 192], &s, &c);
        g_qff[t - 192] = make_float2(c, s);
    }
    {
        int j = t >> 4, k = t & 15;
        for (int m = 0; m < 2; ++m) {
            float cp, sp;
            sincosf(sig_ang[m+1], &sp, &cp);
            float2 acc = make_float2(0.f, 0.f);
            #pragma unroll
            for (int a = 0; a < 16; ++a) {
                float2 uja = sU[j][a];
                float2 uka = sU[k][a];
                float dr = cp, di = (a == 0) ? sp : -sp;
                float2 dc = make_float2(dr*uka.x + di*uka.y, di*uka.x - dr*uka.y);
                acc.x += uja.x*dc.x - uja.y*dc.y;
                acc.y += uja.x*dc.y + uja.y*dc.x;
            }
            g_M[m][j*16 + k] = acc;
        }
        float cp, sp;
        sincosf(sig_ang[3], &sp, &cp);
        float dr = cp, di = (j == 0) ? sp : -sp;
        float2 u2 = sU[k][j];
        g_M[2][j*16 + k] = make_float2(dr*u2.x + di*u2.y, di*u2.x - dr*u2.y);
    }
}

// ------------------------------------------------------- gate primitives ----
// layout: amplitude s: lane = s[4:0], reg = s[7:5] (8 u64/lane), warp = s[9:8].

template<int PB>      // reg-bit RY, PB in 0..2
__device__ __forceinline__ void ry_reg(u64* v, float cc, float ss)
{
    u64 cc2 = pk2(cc, cc), ss2 = pk2(ss, ss), nss2 = pk2(-ss, -ss);
    #pragma unroll
    for (int m = 0; m < 4; ++m) {
        int i0 = ((m >> PB) << (PB+1)) | (m & ((1 << PB) - 1));
        int i1 = i0 | (1 << PB);
        u64 a0 = v[i0], a1 = v[i1];
        v[i0] = fma2(cc2, a0, mul2(nss2, a1));
        v[i1] = fma2(cc2, a1, mul2(ss2, a0));
    }
}

__device__ __forceinline__ void ry_lane(u64* v, int pl, float cc, float ss, int lane)
{
    float sg = ((lane >> pl) & 1) ? ss : -ss;
    u64 cc2 = pk2(cc, cc), sg2 = pk2(sg, sg);
    int mk = 1 << pl;
    #pragma unroll
    for (int q = 0; q < 8; ++q) {
        float2 f = upk(v[q]);
        float px = __shfl_xor_sync(0xffffffffu, f.x, mk);
        float py = __shfl_xor_sync(0xffffffffu, f.y, mk);
        v[q] = fma2(cc2, v[q], mul2(sg2, pk2(px, py)));
    }
}

template<int PCB, int PTB>    // reg-reg CRX
__device__ __forceinline__ void crx_rr(u64* v, float cc, float ss)
{
    u64 cc2 = pk2(cc, cc), ssv2 = pk2(ss, -ss);
    #pragma unroll
    for (int i = 0; i < 8; ++i) {
        if ((((i >> PCB) & 1) == 1) && (((i >> PTB) & 1) == 0)) {
            int i1 = i | (1 << PTB);
            u64 a0 = v[i], a1 = v[i1];
            v[i]  = fma2(cc2, a0, mul2(ssv2, swap2(a1)));
            v[i1] = fma2(cc2, a1, mul2(ssv2, swap2(a0)));
        }
    }
}

// shuffle-target CRX with activity predicate
__device__ __forceinline__ void crx_shfl(u64* v, int pt, bool act, float cc, float ss)
{
    float ccl = act ? cc : 1.f, ssl = act ? ss : 0.f;
    u64 cc2 = pk2(ccl, ccl), ssv2 = pk2(ssl, -ssl);
    int mk = 1 << pt;
    #pragma unroll
    for (int q = 0; q < 8; ++q) {
        float2 f = upk(v[q]);
        float px = __shfl_xor_sync(0xffffffffu, f.x, mk);
        float py = __shfl_xor_sync(0xffffffffu, f.y, mk);
        v[q] = fma2(cc2, v[q], mul2(ssv2, pk2(py, px)));
    }
}

template<int PCB>     // control reg bit, target lane bit
__device__ __forceinline__ void crx_rl(u64* v, int pt, float cc, float ss)
{
    u64 cc2 = pk2(cc, cc), ssv2 = pk2(ss, -ss);
    int mk = 1 << pt;
    #pragma unroll
    for (int q = 0; q < 8; ++q) {
        if ((q >> PCB) & 1) {
            float2 f = upk(v[q]);
            float px = __shfl_xor_sync(0xffffffffu, f.x, mk);
            float py = __shfl_xor_sync(0xffffffffu, f.y, mk);
            v[q] = fma2(cc2, v[q], mul2(ssv2, pk2(py, px)));
        }
    }
}

template<int PTB>     // predicate control, target reg bit
__device__ __forceinline__ void crx_reg_tgt(u64* v, bool act, float cc, float ss)
{
    float ccl = act ? cc : 1.f, ssl = act ? ss : 0.f;
    u64 cc2 = pk2(ccl, ccl), ssv2 = pk2(ssl, -ssl);
    #pragma unroll
    for (int m = 0; m < 4; ++m) {
        int i0 = ((m >> PTB) << (PTB+1)) | (m & ((1 << PTB) - 1));
        int i1 = i0 | (1 << PTB);
        u64 a0 = v[i0], a1 = v[i1];
        v[i0] = fma2(cc2, a0, mul2(ssv2, swap2(a1)));
        v[i1] = fma2(cc2, a1, mul2(ssv2, swap2(a0)));
    }
}

// ----- cross-warp exchange gates (double-buffered smem, 1 bar each) ---------
struct Xch {
    u64* base; int tog; int tid;
    __device__ __forceinline__ u64* next() { u64* p = base + ((tog & 1) << 10); ++tog; return p; }
};

// RY on warp bit wb
__device__ __forceinline__ void ry_warp(u64* v, Xch& X, int wb, float cc, float ss)
{
    u64* b = X.next();
    int tid = X.tid, xv = 32 << wb;
    #pragma unroll
    for (int i = 0; i < 8; ++i) b[i*128 + tid] = v[i];
    __syncthreads();
    float sg = ((tid >> (5 + wb)) & 1) ? ss : -ss;
    u64 cc2 = pk2(cc, cc), sg2 = pk2(sg, sg);
    #pragma unroll
    for (int i = 0; i < 8; ++i)
        v[i] = fma2(cc2, v[i], mul2(sg2, b[i*128 + (tid ^ xv)]));
}

// CRX with target on warp bit twb; act = control predicate (partner has same act)
__device__ __forceinline__ void crx_warp_tgt(u64* v, Xch& X, int twb, bool act, float cc, float ss)
{
    u64* b = X.next();
    int tid = X.tid, xv = 32 << twb;
    #pragma unroll
    for (int i = 0; i < 8; ++i) b[i*128 + tid] = v[i];
    __syncthreads();
    float ccl = act ? cc : 1.f, ssl = act ? ss : 0.f;
    u64 cc2 = pk2(ccl, ccl), ssv2 = pk2(ssl, -ssl);
    #pragma unroll
    for (int i = 0; i < 8; ++i)
        v[i] = fma2(cc2, v[i], mul2(ssv2, swap2(b[i*128 + (tid ^ xv)])));
}

// CRX control on reg bit 2 (regs 4..7), target warp bit twb
__device__ __forceinline__ void crx_rw(u64* v, Xch& X, int twb, float cc, float ss)
{
    u64* b = X.next();
    int tid = X.tid, xv = 32 << twb;
    #pragma unroll
    for (int i = 0; i < 4; ++i) b[i*128 + tid] = v[4 + i];
    __syncthreads();
    u64 cc2 = pk2(cc, cc), ssv2 = pk2(ss, -ss);
    #pragma unroll
    for (int i = 0; i < 4; ++i)
        v[4 + i] = fma2(cc2, v[4 + i], mul2(ssv2, swap2(b[i*128 + (tid ^ xv)])));
}

// -------------------------------------------------------- layer pieces ------
// qubit q acts on s bit 9-q. bits: lane 0-4, reg 5-7 (PB 0-2), warp 8-9 (wb 0-1)
#define SS(A) (sgn*(A).y)

__device__ __forceinline__ void ry_all(u64* v, Xch& X, const float2* __restrict__ ang,
                                       float sgn, int lane)
{
    ry_warp(v, X, 1, ang[0].x, SS(ang[0]));      // q0 -> bit9 (wb1)
    ry_warp(v, X, 0, ang[1].x, SS(ang[1]));      // q1 -> bit8 (wb0)
    ry_reg<2>(v, ang[2].x, SS(ang[2]));          // q2 -> bit7
    ry_reg<1>(v, ang[3].x, SS(ang[3]));
    ry_reg<0>(v, ang[4].x, SS(ang[4]));
    #pragma unroll 1
    for (int pl = 4; pl >= 0; --pl) {            // q5..q9 -> lane bits 4..0
        float2 cs = ang[9 - pl];
        ry_lane(v, pl, cs.x, sgn*cs.y, lane);
    }
}

// ring A: gate k = (ctrl bit k, tgt bit k-1 mod 10), angle ang[k]
__device__ __forceinline__ void ring_a(u64* v, Xch& X, const float2* __restrict__ ang,
                                       float sgn, int lane, int tid, bool rev)
{
    if (!rev) {
        crx_warp_tgt(v, X, 1, lane & 1, ang[0].x, SS(ang[0]));        // c b0, t b9
        crx_shfl(v, 0, (lane >> 1) & 1, ang[1].x, SS(ang[1]));        // c b1, t b0
        crx_shfl(v, 1, (lane >> 2) & 1, ang[2].x, SS(ang[2]));        // c b2, t b1
        crx_shfl(v, 2, (lane >> 3) & 1, ang[3].x, SS(ang[3]));        // c b3, t b2
        crx_shfl(v, 3, (lane >> 4) & 1, ang[4].x, SS(ang[4]));        // c b4, t b3
        crx_rl<0>(v, 4, ang[5].x, SS(ang[5]));                        // c b5(reg0), t b4
        crx_rr<1,0>(v, ang[6].x, SS(ang[6]));                         // c b6, t b5
        crx_rr<2,1>(v, ang[7].x, SS(ang[7]));                         // c b7, t b6
        crx_reg_tgt<2>(v, (tid >> 5) & 1, ang[8].x, SS(ang[8]));      // c b8, t b7
        crx_warp_tgt(v, X, 0, (tid >> 6) & 1, ang[9].x, SS(ang[9]));  // c b9, t b8
    } else {
        crx_warp_tgt(v, X, 0, (tid >> 6) & 1, ang[9].x, SS(ang[9]));
        crx_reg_tgt<2>(v, (tid >> 5) & 1, ang[8].x, SS(ang[8]));
        crx_rr<2,1>(v, ang[7].x, SS(ang[7]));
        crx_rr<1,0>(v, ang[6].x, SS(ang[6]));
        crx_rl<0>(v, 4, ang[5].x, SS(ang[5]));
        crx_shfl(v, 3, (lane >> 4) & 1, ang[4].x, SS(ang[4]));
        crx_shfl(v, 2, (lane >> 3) & 1, ang[3].x, SS(ang[3]));
        crx_shfl(v, 1, (lane >> 2) & 1, ang[2].x, SS(ang[2]));
        crx_shfl(v, 0, (lane >> 1) & 1, ang[1].x, SS(ang[1]));
        crx_warp_tgt(v, X, 1, lane & 1, ang[0].x, SS(ang[0]));
    }
}

// ring B: gates k0(c0,t1) k1(c9,t0) k2(c8,t9) k3(c7,t8) k4(c6,t7)
//               k5(c5,t6) k6(c4,t5) k7(c3,t4) k8(c2,t3) k9(c1,t2)
__device__ __forceinline__ void ring_b(u64* v, Xch& X, const float2* __restrict__ ang,
                                       float sgn, int lane, int tid, bool rev)
{
    if (!rev) {
        crx_shfl(v, 1, lane & 1, ang[0].x, SS(ang[0]));               // c b0, t b1
        crx_shfl(v, 0, (tid >> 6) & 1, ang[1].x, SS(ang[1]));         // c b9, t b0
        crx_warp_tgt(v, X, 1, (tid >> 5) & 1, ang[2].x, SS(ang[2]));  // c b8, t b9
        crx_rw(v, X, 0, ang[3].x, SS(ang[3]));                        // c b7(reg2), t b8
        crx_rr<1,2>(v, ang[4].x, SS(ang[4]));                         // c b6, t b7
        crx_rr<0,1>(v, ang[5].x, SS(ang[5]));                         // c b5, t b6
        crx_reg_tgt<0>(v, (lane >> 4) & 1, ang[6].x, SS(ang[6]));     // c b4, t b5
        crx_shfl(v, 4, (lane >> 3) & 1, ang[7].x, SS(ang[7]));        // c b3, t b4
        crx_shfl(v, 3, (lane >> 2) & 1, ang[8].x, SS(ang[8]));        // c b2, t b3
        crx_shfl(v, 2, (lane >> 1) & 1, ang[9].x, SS(ang[9]));        // c b1, t b2
    } else {
        crx_shfl(v, 2, (lane >> 1) & 1, ang[9].x, SS(ang[9]));
        crx_shfl(v, 3, (lane >> 2) & 1, ang[8].x, SS(ang[8]));
        crx_shfl(v, 4, (lane >> 3) & 1, ang[7].x, SS(ang[7]));
        crx_reg_tgt<0>(v, (lane >> 4) & 1, ang[6].x, SS(ang[6]));
        crx_rr<0,1>(v, ang[5].x, SS(ang[5]));
        crx_rr<1,2>(v, ang[4].x, SS(ang[4]));
        crx_rw(v, X, 0, ang[3].x, SS(ang[3]));
        crx_warp_tgt(v, X, 1, (tid >> 5) & 1, ang[2].x, SS(ang[2]));
        crx_shfl(v, 0, (tid >> 6) & 1, ang[1].x, SS(ang[1]));
        crx_shfl(v, 1, lane & 1, ang[0].x, SS(ang[0]));
    }
}

// ------------------------------------------------------------- select -------
__global__ void __launch_bounds__(128) k_sel_f(int nlayers, int useQff, int initFlag)
{
    int c = blockIdx.x;
    int tid = threadIdx.x;
    int lane = tid & 31;
    const float sgn = 1.f;
    __shared__ float2 sang[80];
    __shared__ u64 xbuf[2048];
    {
        const float2* src = useQff ? g_qff : (g_csn + c*NROTS);
        int ntot = nlayers * 40;
        if (tid < ntot) sang[tid] = src[tid];
    }
    __syncthreads();

    Xch X{xbuf, 0, tid};
    u64 v[8];
    u64* gb = G_STATEU + ((size_t)c << 10);
    int base = (tid >> 5) * 256 + lane;
    if (initFlag) {
        #pragma unroll
        for (int q = 0; q < 8; ++q) v[q] = 0ull;
        if (tid == 0) { float2 f = g_v0[c & 15]; v[0] = pk2(f.x, f.y); }
    } else {
        #pragma unroll
        for (int q = 0; q < 8; ++q) v[q] = gb[base + q*32];
    }

    #pragma unroll 1
    for (int l = 0; l < nlayers; ++l) {
        const float2* a = sang + 40*l;
        ry_all(v, X, a, sgn, lane);
        ring_a(v, X, a + 10, sgn, lane, tid, false);
        ry_all(v, X, a + 20, sgn, lane);
        ring_b(v, X, a + 30, sgn, lane, tid, false);
    }

    #pragma unroll
    for (int q = 0; q < 8; ++q) gb[base + q*32] = v[q];
}

__global__ void __launch_bounds__(128) k_sel_a(int nlayers)
{
    int c = blockIdx.x;
    int tid = threadIdx.x;
    int lane = tid & 31;
    const float sgn = -1.f;
    __shared__ float2 sang[80];
    __shared__ u64 xbuf[2048];
    {
        const float2* src = g_csn + c*NROTS;
        int ntot = nlayers * 40;
        if (tid < ntot) sang[tid] = src[tid];
    }
    __syncthreads();

    Xch X{xbuf, 0, tid};
    u64 v[8];
    u64* gb = G_STATEU + ((size_t)c << 10);
    int base = (tid >> 5) * 256 + lane;
    #pragma unroll
    for (int q = 0; q < 8; ++q) v[q] = gb[base + q*32];

    #pragma unroll 1
    for (int l = nlayers - 1; l >= 0; --l) {
        const float2* a = sang + 40*l;
        ring_b(v, X, a + 30, sgn, lane, tid, true);
        ry_all(v, X, a + 20, sgn, lane);
        ring_a(v, X, a + 10, sgn, lane, tid, true);
        ry_all(v, X, a, sgn, lane);
    }

    #pragma unroll
    for (int q = 0; q < 8; ++q) gb[base + q*32] = v[q];
}

// ---------------------------------------------------------- ancilla mat -----
// Barrier-free shuffle version. Warp = 16 ancilla values x 2 s-values.
// lane = a | (sh<<4). Each lane: load 1 amp, preload M row, 16x shfl matvec.
__global__ void __launch_bounds__(256) k_anc(int mi)
{
    int tid = threadIdx.x;
    int lane = tid & 31;
    int a = lane & 15, hi = lane & 16;
    int w = tid >> 5;
    int blk = blockIdx.x;               // 16 b * 64 s-groups of 16
    int b = blk >> 6;
    int s = ((blk & 63) << 4) + 2*w + (hi >> 4);

    const u64* Mu = (const u64*)(g_M[mi]);
    u64 mrow[16];
    #pragma unroll
    for (int k = 0; k < 16; ++k) mrow[k] = Mu[a*16 + k];

    size_t idx = (((size_t)(b*16 + a)) << 10) + s;
    float2 xf = upk(G_STATEU[idx]);

    u64 acc = 0ull;
    #pragma unroll
    for (int k = 0; k < 16; ++k) {
        float xr = __shfl_sync(0xffffffffu, xf.x, k | hi);
        float xi = __shfl_sync(0xffffffffu, xf.y, k | hi);
        float2 m = upk(mrow[k]);
        acc = fma2(pk2(m.x, m.x), pk2(xr, xi), acc);
        acc = fma2(pk2(m.y, m.y), pk2(-xi, xr), acc);
    }
    G_STATEU[idx] = acc;
}

// ------------------------------------------------- expvals + output GEMM ----
__global__ void __launch_bounds__(640) k_exp_out(const float* __restrict__ W_out,
                                                 const float* __restrict__ b_out,
                                                 float* __restrict__ out)
{
    int b = blockIdx.x;
    int tid = threadIdx.x, w = tid >> 5, lane = tid & 31;
    const float2* st = G_STATE + ((size_t)b << 14);
    __shared__ float red[20][3];
    __shared__ float ex[30];

    {
        int qi = w % 10, half = w / 10;
        int p = 9 - qi;
        float cr = 0.f, ci = 0.f, zz = 0.f;
        int start = half * 4096 + lane;
        #pragma unroll 4
        for (int pk_ = start; pk_ < start - lane + 4096; pk_ += 32) {
            int a = pk_ >> 9, m = pk_ & 511;
            int s0 = ((m >> p) << (p+1)) | (m & ((1 << p) - 1));
            int f0 = (a << 10) | s0;
            float2 a0 = st[f0];
            float2 a1 = st[f0 | (1 << p)];
            cr += a0.x*a1.x + a0.y*a1.y;
            ci += a0.x*a1.y - a0.y*a1.x;
            zz += (a0.x*a0.x + a0.y*a0.y) - (a1.x*a1.x + a1.y*a1.y);
        }
        #pragma unroll
        for (int off = 16; off; off >>= 1) {
            cr += __shfl_down_sync(0xffffffffu, cr, off);
            ci += __shfl_down_sync(0xffffffffu, ci, off);
            zz += __shfl_down_sync(0xffffffffu, zz, off);
        }
        if (lane == 0) { red[w][0] = cr; red[w][1] = ci; red[w][2] = zz; }
    }
    __syncthreads();
    if (tid < 10) {
        ex[tid]      = 2.f*(red[tid][0] + red[tid+10][0]);
        ex[10 + tid] = 2.f*(red[tid][1] + red[tid+10][1]);
        ex[20 + tid] =      red[tid][2] + red[tid+10][2];
    }
    __syncthreads();
    if (tid < ODIM) {
        float acc = b_out[tid];
        #pragma unroll
        for (int j = 0; j < 30; ++j) acc += W_out[tid*30 + j] * ex[j];
        out[b*ODIM + tid] = acc;
    }
}

// ------------------------------------------------------------ launch --------
extern "C" void kernel_launch(void* const* d_in, const int* in_sizes, int n_in,
                              void* d_out, int out_size)
{
    const float* x       = (const float*)d_in[0];
    const float* W_fp    = (const float*)d_in[1];
    const float* b_fp    = (const float*)d_in[2];
    const float* prep_p  = (const float*)d_in[3];
    const float* sig_ang = (const float*)d_in[4];
    const float* qff_p   = (const float*)d_in[5];
    const float* W_out   = (const float*)d_in[6];
    const float* b_out   = (const float*)d_in[7];
    float* out = (float*)d_out;

    k_pre<<<257, 256>>>(x, W_fp, b_fp, prep_p, sig_ang, qff_p);

    k_sel_f<<<256, 128>>>(2, 0, 1);   // k=0 forward (fused init)
    k_anc<<<1024, 256>>>(0);
    k_sel_a<<<256, 128>>>(2);         // k=1 adjoint
    k_anc<<<1024, 256>>>(1);
    k_sel_f<<<256, 128>>>(2, 0, 0);   // k=2 forward
    k_anc<<<1024, 256>>>(2);

    k_sel_f<<<256, 128>>>(1, 1, 0);   // qff layer

    k_exp_out<<<Bsz, 640>>>(W_out, b_out, out);
}

// round 9
// speedup vs baseline: 1.5618x; 1.5618x over previous
#include <cuda_runtime.h>
#include <math.h>

#define Bsz 16
#define Tn 16
#define FDIM 64
#define ODIM 8
#define NQ 10
#define NA 4
#define NROTS 80
#define QROTS 40
#define NS 1024
#define NANC 16
#define STATE_PER_B (NS*NANC)
#define TOTAL_AMPS (Bsz*STATE_PER_B)

typedef unsigned long long u64;

__device__ float4 g_state4[TOTAL_AMPS/2];
#define G_STATE  ((float2*)g_state4)
#define G_STATEU ((u64*)g_state4)
__device__ float2 g_csn[Bsz*Tn*NROTS];
__device__ float2 g_qff[QROTS];
__device__ float2 g_M[3][256];
__device__ float2 g_v0[16];

// ------------------------------------------------------- packed f32x2 ops ---
__device__ __forceinline__ u64 pk2(float x, float y) {
    u64 r; asm("mov.b64 %0, {%1, %2};" : "=l"(r) : "f"(x), "f"(y)); return r;
}
__device__ __forceinline__ float2 upk(u64 a) {
    float2 f; asm("mov.b64 {%0, %1}, %2;" : "=f"(f.x), "=f"(f.y) : "l"(a)); return f;
}
__device__ __forceinline__ u64 mul2(u64 a, u64 b) {
    u64 d; asm("mul.rn.f32x2 %0, %1, %2;" : "=l"(d) : "l"(a), "l"(b)); return d;
}
__device__ __forceinline__ u64 fma2(u64 a, u64 b, u64 c) {
    u64 d; asm("fma.rn.f32x2 %0, %1, %2, %3;" : "=l"(d) : "l"(a), "l"(b), "l"(c)); return d;
}
__device__ __forceinline__ u64 swap2(u64 a) {
    float2 f = upk(a); return pk2(f.y, f.x);
}

// -------------------------------------------------- pre (angles + setup) ----
__global__ void __launch_bounds__(256) k_pre(const float* __restrict__ x,
                                             const float* __restrict__ Wfp,
                                             const float* __restrict__ bfp,
                                             const float* __restrict__ prep_p,
                                             const float* __restrict__ sig_ang,
                                             const float* __restrict__ qff_p)
{
    int tid = threadIdx.x;
    if (blockIdx.x < 256) {
        int bt = blockIdx.x;
        int b = bt >> 4, t = bt & 15;
        __shared__ float h[64];
        if (tid < 64) {
            int f = tid;
            int k = f >> 1;
            float div = expf((float)(2*k) * (-logf(10000.0f) / 64.0f));
            float arg = (float)t * div;
            float pe = (f & 1) ? cosf(arg) : sinf(arg);
            h[f] = x[(b*64 + f)*16 + t] + pe;
        }
        __syncthreads();
        if (tid < NROTS) {
            float acc = bfp[tid];
            const float* w = Wfp + tid*64;
            #pragma unroll
            for (int f = 0; f < 64; ++f) acc += h[f]*w[f];
            float sg = 1.0f / (1.0f + expf(-acc));
            float sn, cs;
            sincosf(3.14159265358979323846f * sg, &sn, &cs);
            g_csn[bt*NROTS + tid] = make_float2(cs, sn);
        }
        return;
    }
    __shared__ float2 sU[16][16];
    int t = tid;
    if (t < 16) {
        float2 v[16];
        #pragma unroll
        for (int i = 0; i < 16; ++i) v[i] = make_float2(0.f, 0.f);
        v[t] = make_float2(1.f, 0.f);
        for (int ly = 0; ly < 4; ++ly) {
            for (int qi = 0; qi < 4; ++qi) {
                int p = 3 - qi;
                float thy = prep_p[(ly*4 + qi)*2 + 0];
                float thz = prep_p[(ly*4 + qi)*2 + 1];
                float c, s;
                sincosf(0.5f*thy, &s, &c);
                for (int m = 0; m < 8; ++m) {
                    int i0 = ((m >> p) << (p+1)) | (m & ((1 << p) - 1));
                    int i1 = i0 | (1 << p);
                    float2 a0 = v[i0], a1 = v[i1];
                    v[i0] = make_float2(c*a0.x - s*a1.x, c*a0.y - s*a1.y);
                    v[i1] = make_float2(s*a0.x + c*a1.x, s*a0.y + c*a1.y);
                }
                float cz, sz;
                sincosf(0.5f*thz, &sz, &cz);
                for (int i = 0; i < 16; ++i) {
                    float im = ((i >> p) & 1) ? sz : -sz;
                    float2 a = v[i];
                    v[i] = make_float2(cz*a.x - im*a.y, cz*a.y + im*a.x);
                }
            }
            for (int i = 0; i < 3; ++i) {
                int pc = 3 - i, pt = 2 - i;
                for (int idx = 0; idx < 16; ++idx) {
                    if (((idx >> pc) & 1) == 1 && ((idx >> pt) & 1) == 0) {
                        int j = idx | (1 << pt);
                        float2 tmp = v[idx]; v[idx] = v[j]; v[j] = tmp;
                    }
                }
            }
        }
        #pragma unroll
        for (int r = 0; r < 16; ++r) sU[r][t] = v[r];
    }
    __syncthreads();
    if (t < 16) {
        float c0, s0;
        sincosf(sig_ang[0], &s0, &c0);
        float2 u = sU[t][0];
        g_v0[t] = make_float2(c0*u.x - s0*u.y, c0*u.y + s0*u.x);
    }
    if (t >= 192 && t < 192 + QROTS) {
        float c, s;
        sincosf(0.5f * qff_p[t - 192], &s, &c);
        g_qff[t - 192] = make_float2(c, s);
    }
    {
        int j = t >> 4, k = t & 15;
        for (int m = 0; m < 2; ++m) {
            float cp, sp;
            sincosf(sig_ang[m+1], &sp, &cp);
            float2 acc = make_float2(0.f, 0.f);
            #pragma unroll
            for (int a = 0; a < 16; ++a) {
                float2 uja = sU[j][a];
                float2 uka = sU[k][a];
                float dr = cp, di = (a == 0) ? sp : -sp;
                float2 dc = make_float2(dr*uka.x + di*uka.y, di*uka.x - dr*uka.y);
                acc.x += uja.x*dc.x - uja.y*dc.y;
                acc.y += uja.x*dc.y + uja.y*dc.x;
            }
            g_M[m][j*16 + k] = acc;
        }
        float cp, sp;
        sincosf(sig_ang[3], &sp, &cp);
        float dr = cp, di = (j == 0) ? sp : -sp;
        float2 u2 = sU[k][j];
        g_M[2][j*16 + k] = make_float2(dr*u2.x + di*u2.y, di*u2.x - dr*u2.y);
    }
}

// ------------------------------------------------------- gate primitives ----
// layout: amplitude s: lane = s[4:0], reg = s[7:5] (8 u64/lane), warp = s[9:8].

template<int PB>      // reg-bit RY, PB in 0..2
__device__ __forceinline__ void ry_reg(u64* v, float cc, float ss)
{
    u64 cc2 = pk2(cc, cc), ss2 = pk2(ss, ss), nss2 = pk2(-ss, -ss);
    #pragma unroll
    for (int m = 0; m < 4; ++m) {
        int i0 = ((m >> PB) << (PB+1)) | (m & ((1 << PB) - 1));
        int i1 = i0 | (1 << PB);
        u64 a0 = v[i0], a1 = v[i1];
        v[i0] = fma2(cc2, a0, mul2(nss2, a1));
        v[i1] = fma2(cc2, a1, mul2(ss2, a0));
    }
}

__device__ __forceinline__ void ry_lane(u64* v, int pl, float cc, float ss, int lane)
{
    float sg = ((lane >> pl) & 1) ? ss : -ss;
    u64 cc2 = pk2(cc, cc), sg2 = pk2(sg, sg);
    int mk = 1 << pl;
    #pragma unroll
    for (int q = 0; q < 8; ++q) {
        float2 f = upk(v[q]);
        float px = __shfl_xor_sync(0xffffffffu, f.x, mk);
        float py = __shfl_xor_sync(0xffffffffu, f.y, mk);
        v[q] = fma2(cc2, v[q], mul2(sg2, pk2(px, py)));
    }
}

template<int PCB, int PTB>    // reg-reg CRX
__device__ __forceinline__ void crx_rr(u64* v, float cc, float ss)
{
    u64 cc2 = pk2(cc, cc), ssv2 = pk2(ss, -ss);
    #pragma unroll
    for (int i = 0; i < 8; ++i) {
        if ((((i >> PCB) & 1) == 1) && (((i >> PTB) & 1) == 0)) {
            int i1 = i | (1 << PTB);
            u64 a0 = v[i], a1 = v[i1];
            v[i]  = fma2(cc2, a0, mul2(ssv2, swap2(a1)));
            v[i1] = fma2(cc2, a1, mul2(ssv2, swap2(a0)));
        }
    }
}

// shuffle-target CRX with activity predicate
__device__ __forceinline__ void crx_shfl(u64* v, int pt, bool act, float cc, float ss)
{
    float ccl = act ? cc : 1.f, ssl = act ? ss : 0.f;
    u64 cc2 = pk2(ccl, ccl), ssv2 = pk2(ssl, -ssl);
    int mk = 1 << pt;
    #pragma unroll
    for (int q = 0; q < 8; ++q) {
        float2 f = upk(v[q]);
        float px = __shfl_xor_sync(0xffffffffu, f.x, mk);
        float py = __shfl_xor_sync(0xffffffffu, f.y, mk);
        v[q] = fma2(cc2, v[q], mul2(ssv2, pk2(py, px)));
    }
}

template<int PCB>     // control reg bit, target lane bit
__device__ __forceinline__ void crx_rl(u64* v, int pt, float cc, float ss)
{
    u64 cc2 = pk2(cc, cc), ssv2 = pk2(ss, -ss);
    int mk = 1 << pt;
    #pragma unroll
    for (int q = 0; q < 8; ++q) {
        if ((q >> PCB) & 1) {
            float2 f = upk(v[q]);
            float px = __shfl_xor_sync(0xffffffffu, f.x, mk);
            float py = __shfl_xor_sync(0xffffffffu, f.y, mk);
            v[q] = fma2(cc2, v[q], mul2(ssv2, pk2(py, px)));
        }
    }
}

template<int PTB>     // predicate control, target reg bit
__device__ __forceinline__ void crx_reg_tgt(u64* v, bool act, float cc, float ss)
{
    float ccl = act ? cc : 1.f, ssl = act ? ss : 0.f;
    u64 cc2 = pk2(ccl, ccl), ssv2 = pk2(ssl, -ssl);
    #pragma unroll
    for (int m = 0; m < 4; ++m) {
        int i0 = ((m >> PTB) << (PTB+1)) | (m & ((1 << PTB) - 1));
        int i1 = i0 | (1 << PTB);
        u64 a0 = v[i0], a1 = v[i1];
        v[i0] = fma2(cc2, a0, mul2(ssv2, swap2(a1)));
        v[i1] = fma2(cc2, a1, mul2(ssv2, swap2(a0)));
    }
}

// ----- cross-warp exchange gates (double-buffered smem, 1 bar each) ---------
struct Xch {
    u64* base; int tog; int tid;
    __device__ __forceinline__ u64* next() { u64* p = base + ((tog & 1) << 10); ++tog; return p; }
};

// RY on warp bit wb
__device__ __forceinline__ void ry_warp(u64* v, Xch& X, int wb, float cc, float ss)
{
    u64* b = X.next();
    int tid = X.tid, xv = 32 << wb;
    #pragma unroll
    for (int i = 0; i < 8; ++i) b[i*128 + tid] = v[i];
    __syncthreads();
    float sg = ((tid >> (5 + wb)) & 1) ? ss : -ss;
    u64 cc2 = pk2(cc, cc), sg2 = pk2(sg, sg);
    #pragma unroll
    for (int i = 0; i < 8; ++i)
        v[i] = fma2(cc2, v[i], mul2(sg2, b[i*128 + (tid ^ xv)]));
}

// CRX with target on warp bit twb; act = control predicate (partner has same act)
__device__ __forceinline__ void crx_warp_tgt(u64* v, Xch& X, int twb, bool act, float cc, float ss)
{
    u64* b = X.next();
    int tid = X.tid, xv = 32 << twb;
    #pragma unroll
    for (int i = 0; i < 8; ++i) b[i*128 + tid] = v[i];
    __syncthreads();
    float ccl = act ? cc : 1.f, ssl = act ? ss : 0.f;
    u64 cc2 = pk2(ccl, ccl), ssv2 = pk2(ssl, -ssl);
    #pragma unroll
    for (int i = 0; i < 8; ++i)
        v[i] = fma2(cc2, v[i], mul2(ssv2, swap2(b[i*128 + (tid ^ xv)])));
}

// CRX control on reg bit 2 (regs 4..7), target warp bit twb
__device__ __forceinline__ void crx_rw(u64* v, Xch& X, int twb, float cc, float ss)
{
    u64* b = X.next();
    int tid = X.tid, xv = 32 << twb;
    #pragma unroll
    for (int i = 0; i < 4; ++i) b[i*128 + tid] = v[4 + i];
    __syncthreads();
    u64 cc2 = pk2(cc, cc), ssv2 = pk2(ss, -ss);
    #pragma unroll
    for (int i = 0; i < 4; ++i)
        v[4 + i] = fma2(cc2, v[4 + i], mul2(ssv2, swap2(b[i*128 + (tid ^ xv)])));
}

// -------------------------------------------------------- layer pieces ------
// qubit q acts on s bit 9-q. bits: lane 0-4, reg 5-7 (PB 0-2), warp 8-9 (wb 0-1)
#define SS(A) (sgn*(A).y)

__device__ __forceinline__ void ry_all(u64* v, Xch& X, const float2* __restrict__ ang,
                                       float sgn, int lane)
{
    ry_warp(v, X, 1, ang[0].x, SS(ang[0]));      // q0 -> bit9 (wb1)
    ry_warp(v, X, 0, ang[1].x, SS(ang[1]));      // q1 -> bit8 (wb0)
    ry_reg<2>(v, ang[2].x, SS(ang[2]));          // q2 -> bit7
    ry_reg<1>(v, ang[3].x, SS(ang[3]));
    ry_reg<0>(v, ang[4].x, SS(ang[4]));
    #pragma unroll 1
    for (int pl = 4; pl >= 0; --pl) {            // q5..q9 -> lane bits 4..0
        float2 cs = ang[9 - pl];
        ry_lane(v, pl, cs.x, sgn*cs.y, lane);
    }
}

// ring A: gate k = (ctrl bit k, tgt bit k-1 mod 10), angle ang[k]
__device__ __forceinline__ void ring_a(u64* v, Xch& X, const float2* __restrict__ ang,
                                       float sgn, int lane, int tid, bool rev)
{
    if (!rev) {
        crx_warp_tgt(v, X, 1, lane & 1, ang[0].x, SS(ang[0]));        // c b0, t b9
        crx_shfl(v, 0, (lane >> 1) & 1, ang[1].x, SS(ang[1]));        // c b1, t b0
        crx_shfl(v, 1, (lane >> 2) & 1, ang[2].x, SS(ang[2]));        // c b2, t b1
        crx_shfl(v, 2, (lane >> 3) & 1, ang[3].x, SS(ang[3]));        // c b3, t b2
        crx_shfl(v, 3, (lane >> 4) & 1, ang[4].x, SS(ang[4]));        // c b4, t b3
        crx_rl<0>(v, 4, ang[5].x, SS(ang[5]));                        // c b5(reg0), t b4
        crx_rr<1,0>(v, ang[6].x, SS(ang[6]));                         // c b6, t b5
        crx_rr<2,1>(v, ang[7].x, SS(ang[7]));                         // c b7, t b6
        crx_reg_tgt<2>(v, (tid >> 5) & 1, ang[8].x, SS(ang[8]));      // c b8, t b7
        crx_warp_tgt(v, X, 0, (tid >> 6) & 1, ang[9].x, SS(ang[9]));  // c b9, t b8
    } else {
        crx_warp_tgt(v, X, 0, (tid >> 6) & 1, ang[9].x, SS(ang[9]));
        crx_reg_tgt<2>(v, (tid >> 5) & 1, ang[8].x, SS(ang[8]));
        crx_rr<2,1>(v, ang[7].x, SS(ang[7]));
        crx_rr<1,0>(v, ang[6].x, SS(ang[6]));
        crx_rl<0>(v, 4, ang[5].x, SS(ang[5]));
        crx_shfl(v, 3, (lane >> 4) & 1, ang[4].x, SS(ang[4]));
        crx_shfl(v, 2, (lane >> 3) & 1, ang[3].x, SS(ang[3]));
        crx_shfl(v, 1, (lane >> 2) & 1, ang[2].x, SS(ang[2]));
        crx_shfl(v, 0, (lane >> 1) & 1, ang[1].x, SS(ang[1]));
        crx_warp_tgt(v, X, 1, lane & 1, ang[0].x, SS(ang[0]));
    }
}

// ring B: gates k0(c0,t1) k1(c9,t0) k2(c8,t9) k3(c7,t8) k4(c6,t7)
//               k5(c5,t6) k6(c4,t5) k7(c3,t4) k8(c2,t3) k9(c1,t2)
__device__ __forceinline__ void ring_b(u64* v, Xch& X, const float2* __restrict__ ang,
                                       float sgn, int lane, int tid, bool rev)
{
    if (!rev) {
        crx_shfl(v, 1, lane & 1, ang[0].x, SS(ang[0]));               // c b0, t b1
        crx_shfl(v, 0, (tid >> 6) & 1, ang[1].x, SS(ang[1]));         // c b9, t b0
        crx_warp_tgt(v, X, 1, (tid >> 5) & 1, ang[2].x, SS(ang[2]));  // c b8, t b9
        crx_rw(v, X, 0, ang[3].x, SS(ang[3]));                        // c b7(reg2), t b8
        crx_rr<1,2>(v, ang[4].x, SS(ang[4]));                         // c b6, t b7
        crx_rr<0,1>(v, ang[5].x, SS(ang[5]));                         // c b5, t b6
        crx_reg_tgt<0>(v, (lane >> 4) & 1, ang[6].x, SS(ang[6]));     // c b4, t b5
        crx_shfl(v, 4, (lane >> 3) & 1, ang[7].x, SS(ang[7]));        // c b3, t b4
        crx_shfl(v, 3, (lane >> 2) & 1, ang[8].x, SS(ang[8]));        // c b2, t b3
        crx_shfl(v, 2, (lane >> 1) & 1, ang[9].x, SS(ang[9]));        // c b1, t b2
    } else {
        crx_shfl(v, 2, (lane >> 1) & 1, ang[9].x, SS(ang[9]));
        crx_shfl(v, 3, (lane >> 2) & 1, ang[8].x, SS(ang[8]));
        crx_shfl(v, 4, (lane >> 3) & 1, ang[7].x, SS(ang[7]));
        crx_reg_tgt<0>(v, (lane >> 4) & 1, ang[6].x, SS(ang[6]));
        crx_rr<0,1>(v, ang[5].x, SS(ang[5]));
        crx_rr<1,2>(v, ang[4].x, SS(ang[4]));
        crx_rw(v, X, 0, ang[3].x, SS(ang[3]));
        crx_warp_tgt(v, X, 1, (tid >> 5) & 1, ang[2].x, SS(ang[2]));
        crx_shfl(v, 0, (tid >> 6) & 1, ang[1].x, SS(ang[1]));
        crx_shfl(v, 1, lane & 1, ang[0].x, SS(ang[0]));
    }
}

// --------------------------------------------- fused load (ancilla matmul) --
// mi = -1: plain load; mi = -2: init; else v = Sum_a M[mi][a_mine][a] * x(b,a,s)
__device__ __forceinline__ void load_state(u64* v, int c, int base, int tid, int mi)
{
    u64* gb = G_STATEU + ((size_t)c << 10);
    if (mi == -2) {
        #pragma unroll
        for (int q = 0; q < 8; ++q) v[q] = 0ull;
        if (tid == 0) { float2 f = g_v0[c & 15]; v[0] = pk2(f.x, f.y); }
    } else if (mi == -1) {
        #pragma unroll
        for (int q = 0; q < 8; ++q) v[q] = gb[base + q*32];
    } else {
        const u64* Mu = (const u64*)(g_M[mi]) + (c & 15)*16;
        const u64* bb = G_STATEU + ((size_t)(c & ~15) << 10);
        u64 mrow[16];
        #pragma unroll
        for (int a = 0; a < 16; ++a) mrow[a] = Mu[a];
        #pragma unroll
        for (int q = 0; q < 8; ++q) {
            u64 acc = 0ull;
            #pragma unroll
            for (int a = 0; a < 16; ++a) {
                u64 xv = bb[(a << 10) + base + q*32];
                float2 m = upk(mrow[a]);
                acc = fma2(pk2(m.x, m.x), xv, acc);
                acc = fma2(pk2(-m.y, m.y), swap2(xv), acc);
            }
            v[q] = acc;
        }
    }
}

// ------------------------------------------------------------- select -------
__global__ void __launch_bounds__(128) k_sel_f(int nlayers, int useQff, int mi)
{
    int c = blockIdx.x;
    int tid = threadIdx.x;
    int lane = tid & 31;
    const float sgn = 1.f;
    __shared__ float2 sang[80];
    __shared__ u64 xbuf[2048];
    {
        const float2* src = useQff ? g_qff : (g_csn + c*NROTS);
        int ntot = nlayers * 40;
        if (tid < ntot) sang[tid] = src[tid];
    }

    u64 v[8];
    int base = (tid >> 5) * 256 + lane;
    load_state(v, c, base, tid, mi);
    __syncthreads();

    Xch X{xbuf, 0, tid};
    #pragma unroll 1
    for (int l = 0; l < nlayers; ++l) {
        const float2* a = sang + 40*l;
        ry_all(v, X, a, sgn, lane);
        ring_a(v, X, a + 10, sgn, lane, tid, false);
        ry_all(v, X, a + 20, sgn, lane);
        ring_b(v, X, a + 30, sgn, lane, tid, false);
    }

    u64* gb = G_STATEU + ((size_t)c << 10);
    #pragma unroll
    for (int q = 0; q < 8; ++q) gb[base + q*32] = v[q];
}

__global__ void __launch_bounds__(128) k_sel_a(int nlayers, int mi)
{
    int c = blockIdx.x;
    int tid = threadIdx.x;
    int lane = tid & 31;
    const float sgn = -1.f;
    __shared__ float2 sang[80];
    __shared__ u64 xbuf[2048];
    {
        const float2* src = g_csn + c*NROTS;
        int ntot = nlayers * 40;
        if (tid < ntot) sang[tid] = src[tid];
    }

    u64 v[8];
    int base = (tid >> 5) * 256 + lane;
    load_state(v, c, base, tid, mi);
    __syncthreads();

    Xch X{xbuf, 0, tid};
    #pragma unroll 1
    for (int l = nlayers - 1; l >= 0; --l) {
        const float2* a = sang + 40*l;
        ring_b(v, X, a + 30, sgn, lane, tid, true);
        ry_all(v, X, a + 20, sgn, lane);
        ring_a(v, X, a + 10, sgn, lane, tid, true);
        ry_all(v, X, a, sgn, lane);
    }

    u64* gb = G_STATEU + ((size_t)c << 10);
    #pragma unroll
    for (int q = 0; q < 8; ++q) gb[base + q*32] = v[q];
}

// ------------------------------------------------- expvals + output GEMM ----
// NOTE: the last ancilla matrix (F = D3 U^H) is fused here via g_M[2].
__global__ void __launch_bounds__(640) k_exp_out(const float* __restrict__ W_out,
                                                 const float* __restrict__ b_out,
                                                 float* __restrict__ out)
{
    int b = blockIdx.x;
    int tid = threadIdx.x, w = tid >> 5, lane = tid & 31;
    const float2* st = G_STATE + ((size_t)b << 14);
    __shared__ float red[20][3];
    __shared__ float ex[30];

    {
        int qi = w % 10, half = w / 10;
        int p = 9 - qi;
        float cr = 0.f, ci = 0.f, zz = 0.f;
        int start = half * 4096 + lane;
        #pragma unroll 4
        for (int pk_ = start; pk_ < start - lane + 4096; pk_ += 32) {
            int a = pk_ >> 9, m = pk_ & 511;
            int s0 = ((m >> p) << (p+1)) | (m & ((1 << p) - 1));
            int f0 = (a << 10) | s0;
            float2 a0 = st[f0];
            float2 a1 = st[f0 | (1 << p)];
            cr += a0.x*a1.x + a0.y*a1.y;
            ci += a0.x*a1.y - a0.y*a1.x;
            zz += (a0.x*a0.x + a0.y*a0.y) - (a1.x*a1.x + a1.y*a1.y);
        }
        #pragma unroll
        for (int off = 16; off; off >>= 1) {
            cr += __shfl_down_sync(0xffffffffu, cr, off);
            ci += __shfl_down_sync(0xffffffffu, ci, off);
            zz += __shfl_down_sync(0xffffffffu, zz, off);
        }
        if (lane == 0) { red[w][0] = cr; red[w][1] = ci; red[w][2] = zz; }
    }
    __syncthreads();
    if (tid < 10) {
        ex[tid]      = 2.f*(red[tid][0] + red[tid+10][0]);
        ex[10 + tid] = 2.f*(red[tid][1] + red[tid+10][1]);
        ex[20 + tid] =      red[tid][2] + red[tid+10][2];
    }
    __syncthreads();
    if (tid < ODIM) {
        float acc = b_out[tid];
        #pragma unroll
        for (int j = 0; j < 30; ++j) acc += W_out[tid*30 + j] * ex[j];
        out[b*ODIM + tid] = acc;
    }
}

// ------------------------------------------------------------ launch --------
extern "C" void kernel_launch(void* const* d_in, const int* in_sizes, int n_in,
                              void* d_out, int out_size)
{
    const float* x       = (const float*)d_in[0];
    const float* W_fp    = (const float*)d_in[1];
    const float* b_fp    = (const float*)d_in[2];
    const float* prep_p  = (const float*)d_in[3];
    const float* sig_ang = (const float*)d_in[4];
    const float* qff_p   = (const float*)d_in[5];
    const float* W_out   = (const float*)d_in[6];
    const float* b_out   = (const float*)d_in[7];
    float* out = (float*)d_out;

    k_pre<<<257, 256>>>(x, W_fp, b_fp, prep_p, sig_ang, qff_p);

    k_sel_f<<<256, 128>>>(2, 0, -2);   // k=0 forward (init)
    k_sel_a<<<256, 128>>>(2, 0);       // k=1 adjoint, fused M0
    k_sel_f<<<256, 128>>>(2, 0, 1);    // k=2 forward, fused M1
    k_sel_f<<<256, 128>>>(1, 1, 2);    // qff layer, fused M2 (=F)

    k_exp_out<<<Bsz, 640>>>(W_out, b_out, out);
}

// round 10
// speedup vs baseline: 1.6562x; 1.0604x over previous
#include <cuda_runtime.h>
#include <math.h>

#define Bsz 16
#define Tn 16
#define FDIM 64
#define ODIM 8
#define NQ 10
#define NA 4
#define NROTS 80
#define QROTS 40
#define NS 1024
#define NANC 16
#define STATE_PER_B (NS*NANC)
#define TOTAL_AMPS (Bsz*STATE_PER_B)

typedef unsigned long long u64;

__device__ float4 g_state4[TOTAL_AMPS/2];
#define G_STATE  ((float2*)g_state4)
#define G_STATEU ((u64*)g_state4)
__device__ float2 g_csn[Bsz*Tn*NROTS];
__device__ float2 g_qff[QROTS];
__device__ float2 g_M[3][256];
__device__ float2 g_v0[16];

// ------------------------------------------------------- packed f32x2 ops ---
__device__ __forceinline__ u64 pk2(float x, float y) {
    u64 r; asm("mov.b64 %0, {%1, %2};" : "=l"(r) : "f"(x), "f"(y)); return r;
}
__device__ __forceinline__ float2 upk(u64 a) {
    float2 f; asm("mov.b64 {%0, %1}, %2;" : "=f"(f.x), "=f"(f.y) : "l"(a)); return f;
}
__device__ __forceinline__ u64 mul2(u64 a, u64 b) {
    u64 d; asm("mul.rn.f32x2 %0, %1, %2;" : "=l"(d) : "l"(a), "l"(b)); return d;
}
__device__ __forceinline__ u64 fma2(u64 a, u64 b, u64 c) {
    u64 d; asm("fma.rn.f32x2 %0, %1, %2, %3;" : "=l"(d) : "l"(a), "l"(b), "l"(c)); return d;
}
__device__ __forceinline__ u64 swap2(u64 a) {
    float2 f = upk(a); return pk2(f.y, f.x);
}

// -------------------------------------------------- pre (angles + setup) ----
__global__ void __launch_bounds__(256) k_pre(const float* __restrict__ x,
                                             const float* __restrict__ Wfp,
                                             const float* __restrict__ bfp,
                                             const float* __restrict__ prep_p,
                                             const float* __restrict__ sig_ang,
                                             const float* __restrict__ qff_p)
{
    int tid = threadIdx.x;
    if (blockIdx.x < 256) {
        int bt = blockIdx.x;
        int b = bt >> 4, t = bt & 15;
        __shared__ float h[64];
        if (tid < 64) {
            int f = tid;
            int k = f >> 1;
            float div = expf((float)(2*k) * (-logf(10000.0f) / 64.0f));
            float arg = (float)t * div;
            float pe = (f & 1) ? cosf(arg) : sinf(arg);
            h[f] = x[(b*64 + f)*16 + t] + pe;
        }
        __syncthreads();
        if (tid < NROTS) {
            float acc = bfp[tid];
            const float* w = Wfp + tid*64;
            #pragma unroll
            for (int f = 0; f < 64; ++f) acc += h[f]*w[f];
            float sg = 1.0f / (1.0f + expf(-acc));
            float sn, cs;
            sincosf(3.14159265358979323846f * sg, &sn, &cs);
            g_csn[bt*NROTS + tid] = make_float2(cs, sn);
        }
        return;
    }
    __shared__ float2 sU[16][16];
    int t = tid;
    if (t < 16) {
        float2 v[16];
        #pragma unroll
        for (int i = 0; i < 16; ++i) v[i] = make_float2(0.f, 0.f);
        v[t] = make_float2(1.f, 0.f);
        for (int ly = 0; ly < 4; ++ly) {
            for (int qi = 0; qi < 4; ++qi) {
                int p = 3 - qi;
                float thy = prep_p[(ly*4 + qi)*2 + 0];
                float thz = prep_p[(ly*4 + qi)*2 + 1];
                float c, s;
                sincosf(0.5f*thy, &s, &c);
                for (int m = 0; m < 8; ++m) {
                    int i0 = ((m >> p) << (p+1)) | (m & ((1 << p) - 1));
                    int i1 = i0 | (1 << p);
                    float2 a0 = v[i0], a1 = v[i1];
                    v[i0] = make_float2(c*a0.x - s*a1.x, c*a0.y - s*a1.y);
                    v[i1] = make_float2(s*a0.x + c*a1.x, s*a0.y + c*a1.y);
                }
                float cz, sz;
                sincosf(0.5f*thz, &sz, &cz);
                for (int i = 0; i < 16; ++i) {
                    float im = ((i >> p) & 1) ? sz : -sz;
                    float2 a = v[i];
                    v[i] = make_float2(cz*a.x - im*a.y, cz*a.y + im*a.x);
                }
            }
            for (int i = 0; i < 3; ++i) {
                int pc = 3 - i, pt = 2 - i;
                for (int idx = 0; idx < 16; ++idx) {
                    if (((idx >> pc) & 1) == 1 && ((idx >> pt) & 1) == 0) {
                        int j = idx | (1 << pt);
                        float2 tmp = v[idx]; v[idx] = v[j]; v[j] = tmp;
                    }
                }
            }
        }
        #pragma unroll
        for (int r = 0; r < 16; ++r) sU[r][t] = v[r];
    }
    __syncthreads();
    if (t < 16) {
        float c0, s0;
        sincosf(sig_ang[0], &s0, &c0);
        float2 u = sU[t][0];
        g_v0[t] = make_float2(c0*u.x - s0*u.y, c0*u.y + s0*u.x);
    }
    if (t >= 192 && t < 192 + QROTS) {
        float c, s;
        sincosf(0.5f * qff_p[t - 192], &s, &c);
        g_qff[t - 192] = make_float2(c, s);
    }
    {
        int j = t >> 4, k = t & 15;
        for (int m = 0; m < 2; ++m) {
            float cp, sp;
            sincosf(sig_ang[m+1], &sp, &cp);
            float2 acc = make_float2(0.f, 0.f);
            #pragma unroll
            for (int a = 0; a < 16; ++a) {
                float2 uja = sU[j][a];
                float2 uka = sU[k][a];
                float dr = cp, di = (a == 0) ? sp : -sp;
                float2 dc = make_float2(dr*uka.x + di*uka.y, di*uka.x - dr*uka.y);
                acc.x += uja.x*dc.x - uja.y*dc.y;
                acc.y += uja.x*dc.y + uja.y*dc.x;
            }
            g_M[m][j*16 + k] = acc;
        }
        float cp, sp;
        sincosf(sig_ang[3], &sp, &cp);
        float dr = cp, di = (j == 0) ? sp : -sp;
        float2 u2 = sU[k][j];
        g_M[2][j*16 + k] = make_float2(dr*u2.x + di*u2.y, di*u2.x - dr*u2.y);
    }
}

// ------------------------------------------------------- gate primitives ----
// layout: amplitude s: lane = s[4:0], reg = s[7:5] (8 u64/lane), warp = s[9:8].

template<int PB>      // reg-bit RY, PB in 0..2
__device__ __forceinline__ void ry_reg(u64* v, float cc, float ss)
{
    u64 cc2 = pk2(cc, cc), ss2 = pk2(ss, ss), nss2 = pk2(-ss, -ss);
    #pragma unroll
    for (int m = 0; m < 4; ++m) {
        int i0 = ((m >> PB) << (PB+1)) | (m & ((1 << PB) - 1));
        int i1 = i0 | (1 << PB);
        u64 a0 = v[i0], a1 = v[i1];
        v[i0] = fma2(cc2, a0, mul2(nss2, a1));
        v[i1] = fma2(cc2, a1, mul2(ss2, a0));
    }
}

__device__ __forceinline__ void ry_lane(u64* v, int pl, float cc, float ss, int lane)
{
    float sg = ((lane >> pl) & 1) ? ss : -ss;
    u64 cc2 = pk2(cc, cc), sg2 = pk2(sg, sg);
    int mk = 1 << pl;
    #pragma unroll
    for (int q = 0; q < 8; ++q) {
        float2 f = upk(v[q]);
        float px = __shfl_xor_sync(0xffffffffu, f.x, mk);
        float py = __shfl_xor_sync(0xffffffffu, f.y, mk);
        v[q] = fma2(cc2, v[q], mul2(sg2, pk2(px, py)));
    }
}

template<int PCB, int PTB>    // reg-reg CRX
__device__ __forceinline__ void crx_rr(u64* v, float cc, float ss)
{
    u64 cc2 = pk2(cc, cc), ssv2 = pk2(ss, -ss);
    #pragma unroll
    for (int i = 0; i < 8; ++i) {
        if ((((i >> PCB) & 1) == 1) && (((i >> PTB) & 1) == 0)) {
            int i1 = i | (1 << PTB);
            u64 a0 = v[i], a1 = v[i1];
            v[i]  = fma2(cc2, a0, mul2(ssv2, swap2(a1)));
            v[i1] = fma2(cc2, a1, mul2(ssv2, swap2(a0)));
        }
    }
}

// shuffle-target CRX with activity predicate
__device__ __forceinline__ void crx_shfl(u64* v, int pt, bool act, float cc, float ss)
{
    float ccl = act ? cc : 1.f, ssl = act ? ss : 0.f;
    u64 cc2 = pk2(ccl, ccl), ssv2 = pk2(ssl, -ssl);
    int mk = 1 << pt;
    #pragma unroll
    for (int q = 0; q < 8; ++q) {
        float2 f = upk(v[q]);
        float px = __shfl_xor_sync(0xffffffffu, f.x, mk);
        float py = __shfl_xor_sync(0xffffffffu, f.y, mk);
        v[q] = fma2(cc2, v[q], mul2(ssv2, pk2(py, px)));
    }
}

template<int PCB>     // control reg bit, target lane bit
__device__ __forceinline__ void crx_rl(u64* v, int pt, float cc, float ss)
{
    u64 cc2 = pk2(cc, cc), ssv2 = pk2(ss, -ss);
    int mk = 1 << pt;
    #pragma unroll
    for (int q = 0; q < 8; ++q) {
        if ((q >> PCB) & 1) {
            float2 f = upk(v[q]);
            float px = __shfl_xor_sync(0xffffffffu, f.x, mk);
            float py = __shfl_xor_sync(0xffffffffu, f.y, mk);
            v[q] = fma2(cc2, v[q], mul2(ssv2, pk2(py, px)));
        }
    }
}

template<int PTB>     // predicate control, target reg bit
__device__ __forceinline__ void crx_reg_tgt(u64* v, bool act, float cc, float ss)
{
    float ccl = act ? cc : 1.f, ssl = act ? ss : 0.f;
    u64 cc2 = pk2(ccl, ccl), ssv2 = pk2(ssl, -ssl);
    #pragma unroll
    for (int m = 0; m < 4; ++m) {
        int i0 = ((m >> PTB) << (PTB+1)) | (m & ((1 << PTB) - 1));
        int i1 = i0 | (1 << PTB);
        u64 a0 = v[i0], a1 = v[i1];
        v[i0] = fma2(cc2, a0, mul2(ssv2, swap2(a1)));
        v[i1] = fma2(cc2, a1, mul2(ssv2, swap2(a0)));
    }
}

// ----- cross-warp exchange gates (double-buffered smem, 1 bar each) ---------
struct Xch {
    u64* base; int tog; int tid;
    __device__ __forceinline__ u64* next() { u64* p = base + ((tog & 1) << 10); ++tog; return p; }
};

// RY on warp bit wb
__device__ __forceinline__ void ry_warp(u64* v, Xch& X, int wb, float cc, float ss)
{
    u64* b = X.next();
    int tid = X.tid, xv = 32 << wb;
    #pragma unroll
    for (int i = 0; i < 8; ++i) b[i*128 + tid] = v[i];
    __syncthreads();
    float sg = ((tid >> (5 + wb)) & 1) ? ss : -ss;
    u64 cc2 = pk2(cc, cc), sg2 = pk2(sg, sg);
    #pragma unroll
    for (int i = 0; i < 8; ++i)
        v[i] = fma2(cc2, v[i], mul2(sg2, b[i*128 + (tid ^ xv)]));
}

// CRX with target on warp bit twb; act = control predicate (partner has same act)
__device__ __forceinline__ void crx_warp_tgt(u64* v, Xch& X, int twb, bool act, float cc, float ss)
{
    u64* b = X.next();
    int tid = X.tid, xv = 32 << twb;
    #pragma unroll
    for (int i = 0; i < 8; ++i) b[i*128 + tid] = v[i];
    __syncthreads();
    float ccl = act ? cc : 1.f, ssl = act ? ss : 0.f;
    u64 cc2 = pk2(ccl, ccl), ssv2 = pk2(ssl, -ssl);
    #pragma unroll
    for (int i = 0; i < 8; ++i)
        v[i] = fma2(cc2, v[i], mul2(ssv2, swap2(b[i*128 + (tid ^ xv)])));
}

// CRX control on reg bit 2 (regs 4..7), target warp bit twb
__device__ __forceinline__ void crx_rw(u64* v, Xch& X, int twb, float cc, float ss)
{
    u64* b = X.next();
    int tid = X.tid, xv = 32 << twb;
    #pragma unroll
    for (int i = 0; i < 4; ++i) b[i*128 + tid] = v[4 + i];
    __syncthreads();
    u64 cc2 = pk2(cc, cc), ssv2 = pk2(ss, -ss);
    #pragma unroll
    for (int i = 0; i < 4; ++i)
        v[4 + i] = fma2(cc2, v[4 + i], mul2(ssv2, swap2(b[i*128 + (tid ^ xv)])));
}

// -------------------------------------------------------- layer pieces ------
// qubit q acts on s bit 9-q. bits: lane 0-4, reg 5-7 (PB 0-2), warp 8-9 (wb 0-1)
#define SS(A) (sgn*(A).y)

__device__ __forceinline__ void ry_all(u64* v, Xch& X, const float2* __restrict__ ang,
                                       float sgn, int lane)
{
    ry_warp(v, X, 1, ang[0].x, SS(ang[0]));      // q0 -> bit9 (wb1)
    ry_warp(v, X, 0, ang[1].x, SS(ang[1]));      // q1 -> bit8 (wb0)
    ry_reg<2>(v, ang[2].x, SS(ang[2]));          // q2 -> bit7
    ry_reg<1>(v, ang[3].x, SS(ang[3]));
    ry_reg<0>(v, ang[4].x, SS(ang[4]));
    #pragma unroll 1
    for (int pl = 4; pl >= 0; --pl) {            // q5..q9 -> lane bits 4..0
        float2 cs = ang[9 - pl];
        ry_lane(v, pl, cs.x, sgn*cs.y, lane);
    }
}

// ring A: gate k = (ctrl bit k, tgt bit k-1 mod 10), angle ang[k]
__device__ __forceinline__ void ring_a(u64* v, Xch& X, const float2* __restrict__ ang,
                                       float sgn, int lane, int tid, bool rev)
{
    if (!rev) {
        crx_warp_tgt(v, X, 1, lane & 1, ang[0].x, SS(ang[0]));        // c b0, t b9
        crx_shfl(v, 0, (lane >> 1) & 1, ang[1].x, SS(ang[1]));        // c b1, t b0
        crx_shfl(v, 1, (lane >> 2) & 1, ang[2].x, SS(ang[2]));        // c b2, t b1
        crx_shfl(v, 2, (lane >> 3) & 1, ang[3].x, SS(ang[3]));        // c b3, t b2
        crx_shfl(v, 3, (lane >> 4) & 1, ang[4].x, SS(ang[4]));        // c b4, t b3
        crx_rl<0>(v, 4, ang[5].x, SS(ang[5]));                        // c b5(reg0), t b4
        crx_rr<1,0>(v, ang[6].x, SS(ang[6]));                         // c b6, t b5
        crx_rr<2,1>(v, ang[7].x, SS(ang[7]));                         // c b7, t b6
        crx_reg_tgt<2>(v, (tid >> 5) & 1, ang[8].x, SS(ang[8]));      // c b8, t b7
        crx_warp_tgt(v, X, 0, (tid >> 6) & 1, ang[9].x, SS(ang[9]));  // c b9, t b8
    } else {
        crx_warp_tgt(v, X, 0, (tid >> 6) & 1, ang[9].x, SS(ang[9]));
        crx_reg_tgt<2>(v, (tid >> 5) & 1, ang[8].x, SS(ang[8]));
        crx_rr<2,1>(v, ang[7].x, SS(ang[7]));
        crx_rr<1,0>(v, ang[6].x, SS(ang[6]));
        crx_rl<0>(v, 4, ang[5].x, SS(ang[5]));
        crx_shfl(v, 3, (lane >> 4) & 1, ang[4].x, SS(ang[4]));
        crx_shfl(v, 2, (lane >> 3) & 1, ang[3].x, SS(ang[3]));
        crx_shfl(v, 1, (lane >> 2) & 1, ang[2].x, SS(ang[2]));
        crx_shfl(v, 0, (lane >> 1) & 1, ang[1].x, SS(ang[1]));
        crx_warp_tgt(v, X, 1, lane & 1, ang[0].x, SS(ang[0]));
    }
}

// ring B: gates k0(c0,t1) k1(c9,t0) k2(c8,t9) k3(c7,t8) k4(c6,t7)
//               k5(c5,t6) k6(c4,t5) k7(c3,t4) k8(c2,t3) k9(c1,t2)
__device__ __forceinline__ void ring_b(u64* v, Xch& X, const float2* __restrict__ ang,
                                       float sgn, int lane, int tid, bool rev)
{
    if (!rev) {
        crx_shfl(v, 1, lane & 1, ang[0].x, SS(ang[0]));               // c b0, t b1
        crx_shfl(v, 0, (tid >> 6) & 1, ang[1].x, SS(ang[1]));         // c b9, t b0
        crx_warp_tgt(v, X, 1, (tid >> 5) & 1, ang[2].x, SS(ang[2]));  // c b8, t b9
        crx_rw(v, X, 0, ang[3].x, SS(ang[3]));                        // c b7(reg2), t b8
        crx_rr<1,2>(v, ang[4].x, SS(ang[4]));                         // c b6, t b7
        crx_rr<0,1>(v, ang[5].x, SS(ang[5]));                         // c b5, t b6
        crx_reg_tgt<0>(v, (lane >> 4) & 1, ang[6].x, SS(ang[6]));     // c b4, t b5
        crx_shfl(v, 4, (lane >> 3) & 1, ang[7].x, SS(ang[7]));        // c b3, t b4
        crx_shfl(v, 3, (lane >> 2) & 1, ang[8].x, SS(ang[8]));        // c b2, t b3
        crx_shfl(v, 2, (lane >> 1) & 1, ang[9].x, SS(ang[9]));        // c b1, t b2
    } else {
        crx_shfl(v, 2, (lane >> 1) & 1, ang[9].x, SS(ang[9]));
        crx_shfl(v, 3, (lane >> 2) & 1, ang[8].x, SS(ang[8]));
        crx_shfl(v, 4, (lane >> 3) & 1, ang[7].x, SS(ang[7]));
        crx_reg_tgt<0>(v, (lane >> 4) & 1, ang[6].x, SS(ang[6]));
        crx_rr<0,1>(v, ang[5].x, SS(ang[5]));
        crx_rr<1,2>(v, ang[4].x, SS(ang[4]));
        crx_rw(v, X, 0, ang[3].x, SS(ang[3]));
        crx_warp_tgt(v, X, 1, (tid >> 5) & 1, ang[2].x, SS(ang[2]));
        crx_shfl(v, 0, (tid >> 6) & 1, ang[1].x, SS(ang[1]));
        crx_shfl(v, 1, lane & 1, ang[0].x, SS(ang[0]));
    }
}

// ------------------------------------------------------------- select -------
__global__ void __launch_bounds__(128) k_sel_f(int nlayers, int useQff, int initFlag)
{
    int c = blockIdx.x;
    int tid = threadIdx.x;
    int lane = tid & 31;
    const float sgn = 1.f;
    __shared__ float2 sang[80];
    __shared__ u64 xbuf[2048];
    {
        const float2* src = useQff ? g_qff : (g_csn + c*NROTS);
        int ntot = nlayers * 40;
        if (tid < ntot) sang[tid] = src[tid];
    }
    __syncthreads();

    Xch X{xbuf, 0, tid};
    u64 v[8];
    u64* gb = G_STATEU + ((size_t)c << 10);
    int base = (tid >> 5) * 256 + lane;
    if (initFlag) {
        #pragma unroll
        for (int q = 0; q < 8; ++q) v[q] = 0ull;
        if (tid == 0) { float2 f = g_v0[c & 15]; v[0] = pk2(f.x, f.y); }
    } else {
        #pragma unroll
        for (int q = 0; q < 8; ++q) v[q] = gb[base + q*32];
    }

    #pragma unroll 1
    for (int l = 0; l < nlayers; ++l) {
        const float2* a = sang + 40*l;
        ry_all(v, X, a, sgn, lane);
        ring_a(v, X, a + 10, sgn, lane, tid, false);
        ry_all(v, X, a + 20, sgn, lane);
        ring_b(v, X, a + 30, sgn, lane, tid, false);
    }

    #pragma unroll
    for (int q = 0; q < 8; ++q) gb[base + q*32] = v[q];
}

__global__ void __launch_bounds__(128) k_sel_a(int nlayers)
{
    int c = blockIdx.x;
    int tid = threadIdx.x;
    int lane = tid & 31;
    const float sgn = -1.f;
    __shared__ float2 sang[80];
    __shared__ u64 xbuf[2048];
    {
        const float2* src = g_csn + c*NROTS;
        int ntot = nlayers * 40;
        if (tid < ntot) sang[tid] = src[tid];
    }
    __syncthreads();

    Xch X{xbuf, 0, tid};
    u64 v[8];
    u64* gb = G_STATEU + ((size_t)c << 10);
    int base = (tid >> 5) * 256 + lane;
    #pragma unroll
    for (int q = 0; q < 8; ++q) v[q] = gb[base + q*32];

    #pragma unroll 1
    for (int l = nlayers - 1; l >= 0; --l) {
        const float2* a = sang + 40*l;
        ring_b(v, X, a + 30, sgn, lane, tid, true);
        ry_all(v, X, a + 20, sgn, lane);
        ring_a(v, X, a + 10, sgn, lane, tid, true);
        ry_all(v, X, a, sgn, lane);
    }

    #pragma unroll
    for (int q = 0; q < 8; ++q) gb[base + q*32] = v[q];
}

// ---------------------------------------------------------- ancilla mat -----
// 1 thread = 1 amplitude. CTA = 512 threads = (16 a) x (32 s).
// Coalesced LDG -> smem tile -> 16x (2 LDS + 2 fma2) -> coalesced STG.
__global__ void __launch_bounds__(512) k_anc(int mi)
{
    __shared__ u64 sx[16*32];      // x tile: [a][sj]
    __shared__ u64 sM[256];        // M row-major [a'][a]
    int tid = threadIdx.x;
    int a  = tid >> 5;             // 0..15
    int sj = tid & 31;             // 0..31
    int blk = blockIdx.x;          // 16 b * 32 s-groups
    int b = blk >> 5;
    int s = ((blk & 31) << 5) + sj;

    size_t idx = (((size_t)(b*16 + a)) << 10) + s;
    u64 xv = G_STATEU[idx];
    sx[a*32 + sj] = xv;
    if (tid < 256) sM[tid] = ((const u64*)g_M[mi])[tid];
    __syncthreads();

    // output for (a' = a, s): acc = Sum_k M[a][k] * x[k][s]
    u64 acc = 0ull;
    #pragma unroll
    for (int k = 0; k < 16; ++k) {
        float2 m = upk(sM[a*16 + k]);
        u64 x2 = sx[k*32 + sj];
        acc = fma2(pk2(m.x, m.x), x2, acc);
        acc = fma2(pk2(-m.y, m.y), swap2(x2), acc);
    }
    G_STATEU[idx] = acc;
}

// ------------------------------------------------- expvals + output GEMM ----
__global__ void __launch_bounds__(640) k_exp_out(const float* __restrict__ W_out,
                                                 const float* __restrict__ b_out,
                                                 float* __restrict__ out)
{
    int b = blockIdx.x;
    int tid = threadIdx.x, w = tid >> 5, lane = tid & 31;
    const float2* st = G_STATE + ((size_t)b << 14);
    __shared__ float red[20][3];
    __shared__ float ex[30];

    {
        int qi = w % 10, half = w / 10;
        int p = 9 - qi;
        float cr = 0.f, ci = 0.f, zz = 0.f;
        int start = half * 4096 + lane;
        #pragma unroll 4
        for (int pk_ = start; pk_ < start - lane + 4096; pk_ += 32) {
            int a = pk_ >> 9, m = pk_ & 511;
            int s0 = ((m >> p) << (p+1)) | (m & ((1 << p) - 1));
            int f0 = (a << 10) | s0;
            float2 a0 = st[f0];
            float2 a1 = st[f0 | (1 << p)];
            cr += a0.x*a1.x + a0.y*a1.y;
            ci += a0.x*a1.y - a0.y*a1.x;
            zz += (a0.x*a0.x + a0.y*a0.y) - (a1.x*a1.x + a1.y*a1.y);
        }
        #pragma unroll
        for (int off = 16; off; off >>= 1) {
            cr += __shfl_down_sync(0xffffffffu, cr, off);
            ci += __shfl_down_sync(0xffffffffu, ci, off);
            zz += __shfl_down_sync(0xffffffffu, zz, off);
        }
        if (lane == 0) { red[w][0] = cr; red[w][1] = ci; red[w][2] = zz; }
    }
    __syncthreads();
    if (tid < 10) {
        ex[tid]      = 2.f*(red[tid][0] + red[tid+10][0]);
        ex[10 + tid] = 2.f*(red[tid][1] + red[tid+10][1]);
        ex[20 + tid] =      red[tid][2] + red[tid+10][2];
    }
    __syncthreads();
    if (tid < ODIM) {
        float acc = b_out[tid];
        #pragma unroll
        for (int j = 0; j < 30; ++j) acc += W_out[tid*30 + j] * ex[j];
        out[b*ODIM + tid] = acc;
    }
}

// ------------------------------------------------------------ launch --------
extern "C" void kernel_launch(void* const* d_in, const int* in_sizes, int n_in,
                              void* d_out, int out_size)
{
    const float* x       = (const float*)d_in[0];
    const float* W_fp    = (const float*)d_in[1];
    const float* b_fp    = (const float*)d_in[2];
    const float* prep_p  = (const float*)d_in[3];
    const float* sig_ang = (const float*)d_in[4];
    const float* qff_p   = (const float*)d_in[5];
    const float* W_out   = (const float*)d_in[6];
    const float* b_out   = (const float*)d_in[7];
    float* out = (float*)d_out;

    k_pre<<<257, 256>>>(x, W_fp, b_fp, prep_p, sig_ang, qff_p);

    k_sel_f<<<256, 128>>>(2, 0, 1);   // k=0 forward (fused init)
    k_anc<<<512, 512>>>(0);
    k_sel_a<<<256, 128>>>(2);         // k=1 adjoint
    k_anc<<<512, 512>>>(1);
    k_sel_f<<<256, 128>>>(2, 0, 0);   // k=2 forward
    k_anc<<<512, 512>>>(2);

    k_sel_f<<<256, 128>>>(1, 1, 0);   // qff layer

    k_exp_out<<<Bsz, 640>>>(W_out, b_out, out);
}